// round 14
// baseline (speedup 1.0000x reference)
#include <cuda_runtime.h>
#include <cuda_fp16.h>
#include <cstdint>
#include <math.h>

#define BB 4
#define SS 2048
#define DD 1024

// Scratch (__device__ globals — allocation-free rule). 16B-aligned for cp.async.
__device__ __align__(256) __half g_qh [(size_t)BB * SS * DD];
__device__ __align__(256) __half g_kh [(size_t)BB * SS * DD];
__device__ __align__(256) __half g_vh [(size_t)BB * SS * DD];
__device__ __align__(256) __half g_WqT[(size_t)DD * DD];
__device__ __align__(256) __half g_WkT[(size_t)DD * DD];
__device__ __align__(256) __half g_WvT[(size_t)DD * DD];
__device__ __align__(256) __half g_Qp [(size_t)BB * SS * DD];
__device__ __align__(256) __half g_Kp [(size_t)BB * SS * DD];
__device__ __align__(256) __half g_Vp [(size_t)BB * SS * DD];
__device__ __align__(256) float  g_Sc [(size_t)BB * SS * SS];
__device__ __align__(256) __half g_Ph [(size_t)BB * SS * SS];

// ---------------------------------------------------------------------------
// PTX helpers
// ---------------------------------------------------------------------------
__device__ __forceinline__ void cp16(uint32_t dst, const void* src) {
    asm volatile("cp.async.cg.shared.global [%0], [%1], 16;" :: "r"(dst), "l"(src));
}
__device__ __forceinline__ void cp_commit() {
    asm volatile("cp.async.commit_group;");
}
__device__ __forceinline__ void ldsm4(uint32_t* r, uint32_t addr) {
    asm volatile("ldmatrix.sync.aligned.m8n8.x4.shared.b16 {%0,%1,%2,%3}, [%4];"
        : "=r"(r[0]), "=r"(r[1]), "=r"(r[2]), "=r"(r[3]) : "r"(addr));
}
__device__ __forceinline__ void ldsm4t(uint32_t* r, uint32_t addr) {
    asm volatile("ldmatrix.sync.aligned.m8n8.x4.trans.shared.b16 {%0,%1,%2,%3}, [%4];"
        : "=r"(r[0]), "=r"(r[1]), "=r"(r[2]), "=r"(r[3]) : "r"(addr));
}
__device__ __forceinline__ void mma_f16(float* c, const uint32_t* a, const uint32_t* b) {
    asm volatile(
        "mma.sync.aligned.m16n8k16.row.col.f32.f16.f16.f32 "
        "{%0,%1,%2,%3}, {%4,%5,%6,%7}, {%8,%9}, {%0,%1,%2,%3};"
        : "+f"(c[0]), "+f"(c[1]), "+f"(c[2]), "+f"(c[3])
        : "r"(a[0]), "r"(a[1]), "r"(a[2]), "r"(a[3]), "r"(b[0]), "r"(b[1]));
}

// SW128 swizzle for 128B logical rows (A and TN-B tiles)
__device__ __forceinline__ uint32_t swz(uint32_t base, int row, int chunk) {
    return base + (uint32_t)(row * 128) + (uint32_t)((chunk ^ (row & 7)) << 4);
}
// Swizzle for 256B logical rows (NN B tile: 64 k-rows x 128 n-cols halves)
__device__ __forceinline__ uint32_t swzNN(uint32_t base, int row, int ch16) {
    return base + (uint32_t)(row * 256) + (uint32_t)((ch16 ^ ((row & 7) << 1)) << 4);
}

// ---------------------------------------------------------------------------
// FP16 tensor-core GEMM.
//   TN (BNN=false): C[m,n] = alpha * sum_k A[m,k]*B[n,k] (+bias), B [N,K] row-major.
//   NN (BNN=true) : C[m,n] = alpha * sum_k A[m,k]*B[k,n],          B [K,N] row-major.
//   128 threads, CTA tile 128x128x64, 4 warps 64x64, 3-stage cp.async,
//   SW128 swizzle, fragment double-buffering. Next-stage cp.async issue is
//   SPREAD across the four k16 mma bursts (quarter per burst).
//   PROJ3: blockIdx.z selects one of 3 (A,B,bias,C) sets; else z = batch.
// ---------------------------------------------------------------------------
#define STAGES 3
#define BK 64
#define TILE_BYTES 16384                    // A: 128x128B;  B(TN): 128x128B; B(NN): 64x256B
#define STAGE_BYTES (2 * TILE_BYTES)        // 32768
#define GEMM_SMEM (STAGES * STAGE_BYTES)    // 98304

template <bool PROJ3, bool BNN, bool HAS_BIAS, bool OUT_HALF>
__global__ __launch_bounds__(128, 2)
void hgemm(const __half* __restrict__ A, const __half* __restrict__ B,
           const float* __restrict__ bias, void* __restrict__ Cv,
           int N, int K, int ldB, float alpha, long sAz, long sBz, long sCz,
           const __half* __restrict__ A1, const __half* __restrict__ B1,
           const float* __restrict__ bias1, void* __restrict__ Cv1,
           const __half* __restrict__ A2, const __half* __restrict__ B2,
           const float* __restrict__ bias2, void* __restrict__ Cv2)
{
    extern __shared__ __align__(1024) char smraw[];
    const int tid  = threadIdx.x;
    const int lane = tid & 31;
    const int warp = tid >> 5;
    const int m0 = blockIdx.y * 128;
    const int n0 = blockIdx.x * 128;
    const int z  = blockIdx.z;

    const __half* Ab;
    const __half* Bb;
    const float*  biasb;
    void*         Cvb;
    if (PROJ3) {
        Ab    = (z == 0) ? A    : (z == 1) ? A1    : A2;
        Bb    = (z == 0) ? B    : (z == 1) ? B1    : B2;
        biasb = (z == 0) ? bias : (z == 1) ? bias1 : bias2;
        Cvb   = (z == 0) ? Cv   : (z == 1) ? Cv1   : Cv2;
    } else {
        Ab    = A + (long)z * sAz;
        Bb    = B + (long)z * sBz;
        biasb = bias;
        Cvb   = Cv;
    }

    const int wm = (warp >> 1) * 64;
    const int wn = (warp & 1) * 64;
    const int r  = lane >> 2;
    const int cc = lane & 3;

    const uint32_t smBase = (uint32_t)__cvta_generic_to_shared(smraw);

    // ldmatrix lane mapping
    const int aRow = lane & 15;
    const int aSub = lane >> 4;
    const int bRow = ((lane >> 4) << 3) + (lane & 7);             // TN
    const int bSub = (lane >> 3) & 1;                             // TN
    const int kLanePart = (((lane >> 3) & 1) << 3) + (lane & 7);  // NN
    const int nLanePart = (lane >> 4);                            // NN

    // Load a quarter (part in [0,4)) of both tiles for one stage.
    auto load_part = [&](int stage, int k0, int part) {
        const uint32_t aS = smBase + (uint32_t)stage * STAGE_BYTES;
        const uint32_t bS = aS + TILE_BYTES;
#pragma unroll
        for (int i = 0; i < 2; i++) {
            const int c = tid + 128 * (part * 2 + i);   // 1024 chunks per tile total
            {   // A tile: 128 m-rows x 128 B
                const int row   = c >> 3;
                const int chunk = c & 7;
                cp16(swz(aS, row, chunk), Ab + (long)(m0 + row) * K + k0 + chunk * 8);
            }
            if (BNN) {   // B tile: 64 k-rows x 256 B
                const int row  = c >> 4;
                const int ch16 = c & 15;
                cp16(swzNN(bS, row, ch16), Bb + (long)(k0 + row) * ldB + n0 + ch16 * 8);
            } else {     // B tile: 128 n-rows x 128 B
                const int row   = c >> 3;
                const int chunk = c & 7;
                cp16(swz(bS, row, chunk), Bb + (long)(n0 + row) * ldB + k0 + chunk * 8);
            }
        }
    };
    auto load_full = [&](int stage, int k0) {
#pragma unroll
        for (int p = 0; p < 4; p++) load_part(stage, k0, p);
    };

    float acc[4][8][4];
#pragma unroll
    for (int mt = 0; mt < 4; mt++)
#pragma unroll
        for (int nt = 0; nt < 8; nt++)
#pragma unroll
            for (int i = 0; i < 4; i++) acc[mt][nt][i] = 0.0f;

    const int KT = K / BK;
    load_full(0, 0);      cp_commit();
    if (KT > 1) { load_full(1, BK); cp_commit(); }

    uint32_t afr[2][4][4], bfr[2][4][4];

    auto loadA = [&](uint32_t f[4][4], uint32_t aS, int ks) {
#pragma unroll
        for (int mt = 0; mt < 4; mt++)
            ldsm4(f[mt], swz(aS, wm + mt * 16 + aRow, ks * 2 + aSub));
    };
    auto loadB = [&](uint32_t f[4][4], uint32_t bS, int ks) {
        if (BNN) {
            const int kl = ks * 16 + kLanePart;
#pragma unroll
            for (int ng = 0; ng < 4; ng++) {
                const int nch = (wn >> 3) + ng * 2 + nLanePart;
                ldsm4t(f[ng], swzNN(bS, kl, nch));
            }
        } else {
#pragma unroll
            for (int ng = 0; ng < 4; ng++)
                ldsm4(f[ng], swz(bS, wn + ng * 16 + bRow, ks * 2 + bSub));
        }
    };

    for (int t = 0; t < KT; t++) {
        if (t + 2 < KT) asm volatile("cp.async.wait_group 1;");
        else            asm volatile("cp.async.wait_group 0;");
        __syncthreads();

        const int stage = t % STAGES;
        const uint32_t aS = smBase + (uint32_t)stage * STAGE_BYTES;
        const uint32_t bS = aS + TILE_BYTES;
        const bool doNext = (t + 2 < KT);
        const int  nStage = (t + 2) % STAGES;
        const int  nK0    = (t + 2) * BK;

        // critical-path fragments first
        loadA(afr[0], aS, 0);
        loadB(bfr[0], bS, 0);

#pragma unroll
        for (int ks = 0; ks < BK / 16; ks++) {
            const int cur = ks & 1;
            const int nxt = cur ^ 1;
            if (ks < BK / 16 - 1) {
                loadA(afr[nxt], aS, ks + 1);
                loadB(bfr[nxt], bS, ks + 1);
            }
            // spread next-stage async loads: one quarter per k16 burst
            if (doNext) load_part(nStage, nK0, ks);
#pragma unroll
            for (int mt = 0; mt < 4; mt++)
#pragma unroll
                for (int nt = 0; nt < 8; nt++)
                    mma_f16(acc[mt][nt], afr[cur][mt], &bfr[cur][nt >> 1][(nt & 1) * 2]);
        }
        if (doNext) cp_commit();
    }

    // epilogue
#pragma unroll
    for (int mt = 0; mt < 4; mt++) {
        const long row0 = m0 + wm + mt * 16 + r;
#pragma unroll
        for (int nt = 0; nt < 8; nt++) {
            const int colb = n0 + wn + nt * 8 + 2 * cc;
            float x0 = acc[mt][nt][0] * alpha;
            float x1 = acc[mt][nt][1] * alpha;
            float x2 = acc[mt][nt][2] * alpha;
            float x3 = acc[mt][nt][3] * alpha;
            if (HAS_BIAS) {
                const float b0 = biasb[colb], b1 = biasb[colb + 1];
                x0 += b0; x1 += b1; x2 += b0; x3 += b1;
            }
            if (OUT_HALF) {
                __half* Cb = (__half*)Cvb + (PROJ3 ? 0 : (long)z * sCz);
                *(__half2*)(Cb + row0 * N + colb)       = __floats2half2_rn(x0, x1);
                *(__half2*)(Cb + (row0 + 8) * N + colb) = __floats2half2_rn(x2, x3);
            } else {
                float* Cb = (float*)Cvb + (PROJ3 ? 0 : (long)z * sCz);
                *(float2*)(Cb + row0 * N + colb)       = make_float2(x0, x1);
                *(float2*)(Cb + (row0 + 8) * N + colb) = make_float2(x2, x3);
            }
        }
    }
}

// ---------------------------------------------------------------------------
// Batched fp32 -> fp16(rn): z selects which of 3 arrays
// ---------------------------------------------------------------------------
__global__ __launch_bounds__(256)
void f2h3_kernel(const float* __restrict__ a0, const float* __restrict__ a1,
                 const float* __restrict__ a2, __half* __restrict__ o0,
                 __half* __restrict__ o1, __half* __restrict__ o2, long n4)
{
    const float* in = (blockIdx.z == 0) ? a0 : (blockIdx.z == 1) ? a1 : a2;
    __half* out     = (blockIdx.z == 0) ? o0 : (blockIdx.z == 1) ? o1 : o2;
    long i = (long)blockIdx.x * blockDim.x + threadIdx.x;
    const long stride = (long)gridDim.x * blockDim.x;
    for (; i < n4; i += stride) {
        float4 v = ((const float4*)in)[i];
        __half2* o = (__half2*)(out + i * 4);
        o[0] = __floats2half2_rn(v.x, v.y);
        o[1] = __floats2half2_rn(v.z, v.w);
    }
}

// ---------------------------------------------------------------------------
// Batched transpose + convert: W f32 [K][N] -> half [N][K] (z selects weight)
// ---------------------------------------------------------------------------
__global__ __launch_bounds__(256)
void wtrans3_kernel(const float* __restrict__ a0, const float* __restrict__ a1,
                    const float* __restrict__ a2, __half* __restrict__ o0,
                    __half* __restrict__ o1, __half* __restrict__ o2)
{
    const float* in = (blockIdx.z == 0) ? a0 : (blockIdx.z == 1) ? a1 : a2;
    __half* out     = (blockIdx.z == 0) ? o0 : (blockIdx.z == 1) ? o1 : o2;
    __shared__ float t[32][33];
    const int bx = blockIdx.x * 32;   // n
    const int by = blockIdx.y * 32;   // k
    const int tx = threadIdx.x, ty = threadIdx.y;
#pragma unroll
    for (int i = ty; i < 32; i += 8)
        t[i][tx] = in[(long)(by + i) * DD + bx + tx];
    __syncthreads();
#pragma unroll
    for (int i = ty; i < 32; i += 8)
        out[(long)(bx + i) * DD + by + tx] = __float2half_rn(t[tx][i]);
}

// ---------------------------------------------------------------------------
// Row softmax over 2048 fp32 cols -> fp16 probabilities (vectorized)
// ---------------------------------------------------------------------------
__global__ __launch_bounds__(256)
void softmax2048_h(const float* __restrict__ S, __half* __restrict__ P)
{
    const float4* row = (const float4*)(S + (long)blockIdx.x * SS);
    uint2*        po  = (uint2*)(P + (long)blockIdx.x * SS);
    const int t = threadIdx.x;

    float4 v4[2];
    float v[8];
    float mx = -1e30f;
#pragma unroll
    for (int i = 0; i < 2; i++) {
        v4[i] = row[t + i * 256];
        v[i*4+0] = v4[i].x; v[i*4+1] = v4[i].y; v[i*4+2] = v4[i].z; v[i*4+3] = v4[i].w;
    }
#pragma unroll
    for (int i = 0; i < 8; i++) mx = fmaxf(mx, v[i]);
#pragma unroll
    for (int o = 16; o > 0; o >>= 1)
        mx = fmaxf(mx, __shfl_xor_sync(0xFFFFFFFFu, mx, o));

    __shared__ float red[8];
    if ((t & 31) == 0) red[t >> 5] = mx;
    __syncthreads();
    float bmax = red[0];
#pragma unroll
    for (int i = 1; i < 8; i++) bmax = fmaxf(bmax, red[i]);
    __syncthreads();

    float sum = 0.0f;
#pragma unroll
    for (int i = 0; i < 8; i++) {
        v[i] = __expf(v[i] - bmax);
        sum += v[i];
    }
#pragma unroll
    for (int o = 16; o > 0; o >>= 1)
        sum += __shfl_xor_sync(0xFFFFFFFFu, sum, o);
    if ((t & 31) == 0) red[t >> 5] = sum;
    __syncthreads();
    float tot = 0.0f;
#pragma unroll
    for (int i = 0; i < 8; i++) tot += red[i];

    const float inv = __frcp_rn(tot);
#pragma unroll
    for (int i = 0; i < 2; i++) {
        __half2 h0 = __floats2half2_rn(v[i*4+0] * inv, v[i*4+1] * inv);
        __half2 h1 = __floats2half2_rn(v[i*4+2] * inv, v[i*4+3] * inv);
        uint2 u;
        u.x = *(uint32_t*)&h0;
        u.y = *(uint32_t*)&h1;
        po[t + i * 256] = u;
    }
}

// ---------------------------------------------------------------------------
extern "C" void kernel_launch(void* const* d_in, const int* in_sizes, int n_in,
                              void* d_out, int out_size)
{
    const float* q  = (const float*)d_in[0];
    const float* k  = (const float*)d_in[1];
    const float* v  = (const float*)d_in[2];
    const float* Wq = (const float*)d_in[3];
    const float* bq = (const float*)d_in[4];
    const float* Wk = (const float*)d_in[5];
    const float* bk = (const float*)d_in[6];
    const float* Wv = (const float*)d_in[7];
    const float* bv = (const float*)d_in[8];
    float* out = (float*)d_out;

    __half *qh, *kh, *vh, *WqT, *WkT, *WvT, *Qp, *Kp, *Vp, *Ph;
    float *Sc;
    cudaGetSymbolAddress((void**)&qh,  g_qh);
    cudaGetSymbolAddress((void**)&kh,  g_kh);
    cudaGetSymbolAddress((void**)&vh,  g_vh);
    cudaGetSymbolAddress((void**)&WqT, g_WqT);
    cudaGetSymbolAddress((void**)&WkT, g_WkT);
    cudaGetSymbolAddress((void**)&WvT, g_WvT);
    cudaGetSymbolAddress((void**)&Qp,  g_Qp);
    cudaGetSymbolAddress((void**)&Kp,  g_Kp);
    cudaGetSymbolAddress((void**)&Vp,  g_Vp);
    cudaGetSymbolAddress((void**)&Sc,  g_Sc);
    cudaGetSymbolAddress((void**)&Ph,  g_Ph);

    cudaFuncSetAttribute(hgemm<true,  false, true,  true >, cudaFuncAttributeMaxDynamicSharedMemorySize, GEMM_SMEM);
    cudaFuncSetAttribute(hgemm<false, false, false, false>, cudaFuncAttributeMaxDynamicSharedMemorySize, GEMM_SMEM);
    cudaFuncSetAttribute(hgemm<false, true,  false, false>, cudaFuncAttributeMaxDynamicSharedMemorySize, GEMM_SMEM);

    const long nQKV = (long)BB * SS * DD;

    // 1: convert q/k/v to fp16 (one launch, grid.z = 3)
    {
        dim3 g(1024, 1, 3);
        f2h3_kernel<<<g, 256>>>(q, k, v, qh, kh, vh, nQKV / 4);
    }
    // 2: transpose+convert weights (one launch, grid.z = 3)
    {
        dim3 g(32, 32, 3), b(32, 8);
        wtrans3_kernel<<<g, b>>>(Wq, Wk, Wv, WqT, WkT, WvT);
    }

    const dim3 blk(128);

    // 3: Projections, batched into ONE launch (z selects q/k/v triple)
    {
        dim3 g(DD / 128, (BB * SS) / 128, 3);
        hgemm<true, false, true, true><<<g, blk, GEMM_SMEM>>>(
            qh, WqT, bq, Qp, DD, DD, DD, 1.0f, 0, 0, 0,
            kh, WkT, bk, Kp,
            vh, WvT, bv, Vp);
    }

    // 4: Scores (TN, f32 out): per batch M=N=2048, K=1024, alpha=1/32
    {
        dim3 g(SS / 128, SS / 128, BB);
        hgemm<false, false, false, false><<<g, blk, GEMM_SMEM>>>(
            Qp, Kp, nullptr, Sc, SS, DD, DD, 0.03125f,
            (long)SS * DD, (long)SS * DD, (long)SS * SS,
            nullptr, nullptr, nullptr, nullptr,
            nullptr, nullptr, nullptr, nullptr);
    }

    // 5: Softmax (f32 -> f16 probs)
    softmax2048_h<<<BB * SS, 256>>>(Sc, Ph);

    // 6: PV (NN, f32 out): A=Ph [S,S], B=Vp [S,D] k-major; M=2048, N=1024, K=2048
    {
        dim3 g(DD / 128, SS / 128, BB);
        hgemm<false, true, false, false><<<g, blk, GEMM_SMEM>>>(
            Ph, Vp, nullptr, out, DD, SS, DD, 1.0f,
            (long)SS * SS, (long)SS * DD, (long)SS * DD,
            nullptr, nullptr, nullptr, nullptr,
            nullptr, nullptr, nullptr, nullptr);
    }
}

// round 15
// speedup vs baseline: 1.1535x; 1.1535x over previous
#include <cuda_runtime.h>
#include <cuda_fp16.h>
#include <cstdint>
#include <math.h>

#define BB 4
#define SS 2048
#define DD 1024

// Scratch (__device__ globals — allocation-free rule). 16B-aligned for cp.async.
__device__ __align__(256) __half g_qh [(size_t)BB * SS * DD];
__device__ __align__(256) __half g_kh [(size_t)BB * SS * DD];
__device__ __align__(256) __half g_vh [(size_t)BB * SS * DD];
__device__ __align__(256) __half g_WqT[(size_t)DD * DD];
__device__ __align__(256) __half g_WkT[(size_t)DD * DD];
__device__ __align__(256) __half g_WvT[(size_t)DD * DD];
__device__ __align__(256) __half g_Qp [(size_t)BB * SS * DD];
__device__ __align__(256) __half g_Kp [(size_t)BB * SS * DD];
__device__ __align__(256) __half g_Vp [(size_t)BB * SS * DD];
__device__ __align__(256) float  g_Sc [(size_t)BB * SS * SS];
__device__ __align__(256) __half g_Ph [(size_t)BB * SS * SS];

// ---------------------------------------------------------------------------
// PTX helpers
// ---------------------------------------------------------------------------
__device__ __forceinline__ void cp16(uint32_t dst, const void* src) {
    asm volatile("cp.async.cg.shared.global [%0], [%1], 16;" :: "r"(dst), "l"(src));
}
__device__ __forceinline__ void cp_commit() {
    asm volatile("cp.async.commit_group;");
}
__device__ __forceinline__ void ldsm4(uint32_t* r, uint32_t addr) {
    asm volatile("ldmatrix.sync.aligned.m8n8.x4.shared.b16 {%0,%1,%2,%3}, [%4];"
        : "=r"(r[0]), "=r"(r[1]), "=r"(r[2]), "=r"(r[3]) : "r"(addr));
}
__device__ __forceinline__ void ldsm4t(uint32_t* r, uint32_t addr) {
    asm volatile("ldmatrix.sync.aligned.m8n8.x4.trans.shared.b16 {%0,%1,%2,%3}, [%4];"
        : "=r"(r[0]), "=r"(r[1]), "=r"(r[2]), "=r"(r[3]) : "r"(addr));
}
__device__ __forceinline__ void mma_f16(float* c, const uint32_t* a, const uint32_t* b) {
    asm volatile(
        "mma.sync.aligned.m16n8k16.row.col.f32.f16.f16.f32 "
        "{%0,%1,%2,%3}, {%4,%5,%6,%7}, {%8,%9}, {%0,%1,%2,%3};"
        : "+f"(c[0]), "+f"(c[1]), "+f"(c[2]), "+f"(c[3])
        : "r"(a[0]), "r"(a[1]), "r"(a[2]), "r"(a[3]), "r"(b[0]), "r"(b[1]));
}

// SW128 swizzle for 128B logical rows (A and TN-B tiles)
__device__ __forceinline__ uint32_t swz(uint32_t base, int row, int chunk) {
    return base + (uint32_t)(row * 128) + (uint32_t)((chunk ^ (row & 7)) << 4);
}
// Swizzle for 256B logical rows (NN B tile: 64 k-rows x 128 n-cols halves)
__device__ __forceinline__ uint32_t swzNN(uint32_t base, int row, int ch16) {
    return base + (uint32_t)(row * 256) + (uint32_t)((ch16 ^ ((row & 7) << 1)) << 4);
}

// ---------------------------------------------------------------------------
// FP16 tensor-core GEMM.
//   TN (BNN=false): C[m,n] = alpha * sum_k A[m,k]*B[n,k] (+bias), B [N,K] row-major.
//   NN (BNN=true) : C[m,n] = alpha * sum_k A[m,k]*B[k,n],          B [K,N] row-major.
//   128 threads, CTA tile 128x128x64, 4 warps 64x64, 3-stage cp.async,
//   SW128 swizzle, fragment double-buffering.
//   PROJ3: blockIdx.z selects one of 3 (A,B,bias,C) sets; else z = batch.
// ---------------------------------------------------------------------------
#define STAGES 3
#define BK 64
#define TILE_BYTES 16384                    // A: 128x128B;  B(TN): 128x128B; B(NN): 64x256B
#define STAGE_BYTES (2 * TILE_BYTES)        // 32768
#define GEMM_SMEM (STAGES * STAGE_BYTES)    // 98304

template <bool PROJ3, bool BNN, bool HAS_BIAS, bool OUT_HALF>
__global__ __launch_bounds__(128, 2)
void hgemm(const __half* __restrict__ A, const __half* __restrict__ B,
           const float* __restrict__ bias, void* __restrict__ Cv,
           int N, int K, int ldB, float alpha, long sAz, long sBz, long sCz,
           const __half* __restrict__ A1, const __half* __restrict__ B1,
           const float* __restrict__ bias1, void* __restrict__ Cv1,
           const __half* __restrict__ A2, const __half* __restrict__ B2,
           const float* __restrict__ bias2, void* __restrict__ Cv2)
{
    extern __shared__ __align__(1024) char smraw[];
    const int tid  = threadIdx.x;
    const int lane = tid & 31;
    const int warp = tid >> 5;
    const int m0 = blockIdx.y * 128;
    const int n0 = blockIdx.x * 128;
    const int z  = blockIdx.z;

    const __half* Ab;
    const __half* Bb;
    const float*  biasb;
    void*         Cvb;
    if (PROJ3) {
        Ab    = (z == 0) ? A    : (z == 1) ? A1    : A2;
        Bb    = (z == 0) ? B    : (z == 1) ? B1    : B2;
        biasb = (z == 0) ? bias : (z == 1) ? bias1 : bias2;
        Cvb   = (z == 0) ? Cv   : (z == 1) ? Cv1   : Cv2;
    } else {
        Ab    = A + (long)z * sAz;
        Bb    = B + (long)z * sBz;
        biasb = bias;
        Cvb   = Cv;
    }

    const int wm = (warp >> 1) * 64;
    const int wn = (warp & 1) * 64;
    const int r  = lane >> 2;
    const int cc = lane & 3;

    const uint32_t smBase = (uint32_t)__cvta_generic_to_shared(smraw);

    // ldmatrix lane mapping
    const int aRow = lane & 15;
    const int aSub = lane >> 4;
    const int bRow = ((lane >> 4) << 3) + (lane & 7);             // TN
    const int bSub = (lane >> 3) & 1;                             // TN
    const int kLanePart = (((lane >> 3) & 1) << 3) + (lane & 7);  // NN
    const int nLanePart = (lane >> 4);                            // NN

    auto load_tiles = [&](int stage, int k0) {
        const uint32_t aS = smBase + (uint32_t)stage * STAGE_BYTES;
        const uint32_t bS = aS + TILE_BYTES;
#pragma unroll
        for (int i = 0; i < 8; i++) {
            const int c = tid + 128 * i;                  // 1024 x 16B chunks per tile
            {   // A tile: 128 m-rows x 128 B
                const int row   = c >> 3;
                const int chunk = c & 7;
                cp16(swz(aS, row, chunk), Ab + (long)(m0 + row) * K + k0 + chunk * 8);
            }
            if (BNN) {   // B tile: 64 k-rows x 256 B
                const int row  = c >> 4;
                const int ch16 = c & 15;
                cp16(swzNN(bS, row, ch16), Bb + (long)(k0 + row) * ldB + n0 + ch16 * 8);
            } else {     // B tile: 128 n-rows x 128 B
                const int row   = c >> 3;
                const int chunk = c & 7;
                cp16(swz(bS, row, chunk), Bb + (long)(n0 + row) * ldB + k0 + chunk * 8);
            }
        }
    };

    float acc[4][8][4];
#pragma unroll
    for (int mt = 0; mt < 4; mt++)
#pragma unroll
        for (int nt = 0; nt < 8; nt++)
#pragma unroll
            for (int i = 0; i < 4; i++) acc[mt][nt][i] = 0.0f;

    const int KT = K / BK;
    load_tiles(0, 0);      cp_commit();
    if (KT > 1) { load_tiles(1, BK); cp_commit(); }

    uint32_t afr[2][4][4], bfr[2][4][4];

    auto loadA = [&](uint32_t f[4][4], uint32_t aS, int ks) {
#pragma unroll
        for (int mt = 0; mt < 4; mt++)
            ldsm4(f[mt], swz(aS, wm + mt * 16 + aRow, ks * 2 + aSub));
    };
    auto loadB = [&](uint32_t f[4][4], uint32_t bS, int ks) {
        if (BNN) {
            const int kl = ks * 16 + kLanePart;
#pragma unroll
            for (int ng = 0; ng < 4; ng++) {
                const int nch = (wn >> 3) + ng * 2 + nLanePart;
                ldsm4t(f[ng], swzNN(bS, kl, nch));
            }
        } else {
#pragma unroll
            for (int ng = 0; ng < 4; ng++)
                ldsm4(f[ng], swz(bS, wn + ng * 16 + bRow, ks * 2 + bSub));
        }
    };

    for (int t = 0; t < KT; t++) {
        if (t + 2 < KT) asm volatile("cp.async.wait_group 1;");
        else            asm volatile("cp.async.wait_group 0;");
        __syncthreads();

        const int stage = t % STAGES;
        const uint32_t aS = smBase + (uint32_t)stage * STAGE_BYTES;
        const uint32_t bS = aS + TILE_BYTES;

        // critical-path fragments first...
        loadA(afr[0], aS, 0);
        loadB(bfr[0], bS, 0);

        // ...then next-stage async loads (off critical path)
        if (t + 2 < KT) { load_tiles((t + 2) % STAGES, (t + 2) * BK); cp_commit(); }

#pragma unroll
        for (int ks = 0; ks < BK / 16; ks++) {
            const int cur = ks & 1;
            const int nxt = cur ^ 1;
            if (ks < BK / 16 - 1) {
                loadA(afr[nxt], aS, ks + 1);
                loadB(bfr[nxt], bS, ks + 1);
            }
#pragma unroll
            for (int mt = 0; mt < 4; mt++)
#pragma unroll
                for (int nt = 0; nt < 8; nt++)
                    mma_f16(acc[mt][nt], afr[cur][mt], &bfr[cur][nt >> 1][(nt & 1) * 2]);
        }
    }

    // epilogue
#pragma unroll
    for (int mt = 0; mt < 4; mt++) {
        const long row0 = m0 + wm + mt * 16 + r;
#pragma unroll
        for (int nt = 0; nt < 8; nt++) {
            const int colb = n0 + wn + nt * 8 + 2 * cc;
            float x0 = acc[mt][nt][0] * alpha;
            float x1 = acc[mt][nt][1] * alpha;
            float x2 = acc[mt][nt][2] * alpha;
            float x3 = acc[mt][nt][3] * alpha;
            if (HAS_BIAS) {
                const float b0 = biasb[colb], b1 = biasb[colb + 1];
                x0 += b0; x1 += b1; x2 += b0; x3 += b1;
            }
            if (OUT_HALF) {
                __half* Cb = (__half*)Cvb + (PROJ3 ? 0 : (long)z * sCz);
                *(__half2*)(Cb + row0 * N + colb)       = __floats2half2_rn(x0, x1);
                *(__half2*)(Cb + (row0 + 8) * N + colb) = __floats2half2_rn(x2, x3);
            } else {
                float* Cb = (float*)Cvb + (PROJ3 ? 0 : (long)z * sCz);
                *(float2*)(Cb + row0 * N + colb)       = make_float2(x0, x1);
                *(float2*)(Cb + (row0 + 8) * N + colb) = make_float2(x2, x3);
            }
        }
    }
}

// ---------------------------------------------------------------------------
// Batched fp32 -> fp16(rn): z selects which of 3 arrays
// ---------------------------------------------------------------------------
__global__ __launch_bounds__(256)
void f2h3_kernel(const float* __restrict__ a0, const float* __restrict__ a1,
                 const float* __restrict__ a2, __half* __restrict__ o0,
                 __half* __restrict__ o1, __half* __restrict__ o2, long n4)
{
    const float* in = (blockIdx.z == 0) ? a0 : (blockIdx.z == 1) ? a1 : a2;
    __half* out     = (blockIdx.z == 0) ? o0 : (blockIdx.z == 1) ? o1 : o2;
    long i = (long)blockIdx.x * blockDim.x + threadIdx.x;
    const long stride = (long)gridDim.x * blockDim.x;
    for (; i < n4; i += stride) {
        float4 v = ((const float4*)in)[i];
        __half2* o = (__half2*)(out + i * 4);
        o[0] = __floats2half2_rn(v.x, v.y);
        o[1] = __floats2half2_rn(v.z, v.w);
    }
}

// ---------------------------------------------------------------------------
// Batched transpose + convert: W f32 [K][N] -> half [N][K] (z selects weight)
// ---------------------------------------------------------------------------
__global__ __launch_bounds__(256)
void wtrans3_kernel(const float* __restrict__ a0, const float* __restrict__ a1,
                    const float* __restrict__ a2, __half* __restrict__ o0,
                    __half* __restrict__ o1, __half* __restrict__ o2)
{
    const float* in = (blockIdx.z == 0) ? a0 : (blockIdx.z == 1) ? a1 : a2;
    __half* out     = (blockIdx.z == 0) ? o0 : (blockIdx.z == 1) ? o1 : o2;
    __shared__ float t[32][33];
    const int bx = blockIdx.x * 32;   // n
    const int by = blockIdx.y * 32;   // k
    const int tx = threadIdx.x, ty = threadIdx.y;
#pragma unroll
    for (int i = ty; i < 32; i += 8)
        t[i][tx] = in[(long)(by + i) * DD + bx + tx];
    __syncthreads();
#pragma unroll
    for (int i = ty; i < 32; i += 8)
        out[(long)(bx + i) * DD + by + tx] = __float2half_rn(t[tx][i]);
}

// ---------------------------------------------------------------------------
// Row softmax over 2048 fp32 cols -> fp16 probabilities (vectorized)
// ---------------------------------------------------------------------------
__global__ __launch_bounds__(256)
void softmax2048_h(const float* __restrict__ S, __half* __restrict__ P)
{
    const float4* row = (const float4*)(S + (long)blockIdx.x * SS);
    uint2*        po  = (uint2*)(P + (long)blockIdx.x * SS);
    const int t = threadIdx.x;

    float4 v4[2];
    float v[8];
    float mx = -1e30f;
#pragma unroll
    for (int i = 0; i < 2; i++) {
        v4[i] = row[t + i * 256];
        v[i*4+0] = v4[i].x; v[i*4+1] = v4[i].y; v[i*4+2] = v4[i].z; v[i*4+3] = v4[i].w;
    }
#pragma unroll
    for (int i = 0; i < 8; i++) mx = fmaxf(mx, v[i]);
#pragma unroll
    for (int o = 16; o > 0; o >>= 1)
        mx = fmaxf(mx, __shfl_xor_sync(0xFFFFFFFFu, mx, o));

    __shared__ float red[8];
    if ((t & 31) == 0) red[t >> 5] = mx;
    __syncthreads();
    float bmax = red[0];
#pragma unroll
    for (int i = 1; i < 8; i++) bmax = fmaxf(bmax, red[i]);
    __syncthreads();

    float sum = 0.0f;
#pragma unroll
    for (int i = 0; i < 8; i++) {
        v[i] = __expf(v[i] - bmax);
        sum += v[i];
    }
#pragma unroll
    for (int o = 16; o > 0; o >>= 1)
        sum += __shfl_xor_sync(0xFFFFFFFFu, sum, o);
    if ((t & 31) == 0) red[t >> 5] = sum;
    __syncthreads();
    float tot = 0.0f;
#pragma unroll
    for (int i = 0; i < 8; i++) tot += red[i];

    const float inv = __frcp_rn(tot);
#pragma unroll
    for (int i = 0; i < 2; i++) {
        __half2 h0 = __floats2half2_rn(v[i*4+0] * inv, v[i*4+1] * inv);
        __half2 h1 = __floats2half2_rn(v[i*4+2] * inv, v[i*4+3] * inv);
        uint2 u;
        u.x = *(uint32_t*)&h0;
        u.y = *(uint32_t*)&h1;
        po[t + i * 256] = u;
    }
}

// ---------------------------------------------------------------------------
extern "C" void kernel_launch(void* const* d_in, const int* in_sizes, int n_in,
                              void* d_out, int out_size)
{
    const float* q  = (const float*)d_in[0];
    const float* k  = (const float*)d_in[1];
    const float* v  = (const float*)d_in[2];
    const float* Wq = (const float*)d_in[3];
    const float* bq = (const float*)d_in[4];
    const float* Wk = (const float*)d_in[5];
    const float* bk = (const float*)d_in[6];
    const float* Wv = (const float*)d_in[7];
    const float* bv = (const float*)d_in[8];
    float* out = (float*)d_out;

    __half *qh, *kh, *vh, *WqT, *WkT, *WvT, *Qp, *Kp, *Vp, *Ph;
    float *Sc;
    cudaGetSymbolAddress((void**)&qh,  g_qh);
    cudaGetSymbolAddress((void**)&kh,  g_kh);
    cudaGetSymbolAddress((void**)&vh,  g_vh);
    cudaGetSymbolAddress((void**)&WqT, g_WqT);
    cudaGetSymbolAddress((void**)&WkT, g_WkT);
    cudaGetSymbolAddress((void**)&WvT, g_WvT);
    cudaGetSymbolAddress((void**)&Qp,  g_Qp);
    cudaGetSymbolAddress((void**)&Kp,  g_Kp);
    cudaGetSymbolAddress((void**)&Vp,  g_Vp);
    cudaGetSymbolAddress((void**)&Sc,  g_Sc);
    cudaGetSymbolAddress((void**)&Ph,  g_Ph);

    cudaFuncSetAttribute(hgemm<true,  false, true,  true >, cudaFuncAttributeMaxDynamicSharedMemorySize, GEMM_SMEM);
    cudaFuncSetAttribute(hgemm<false, false, false, false>, cudaFuncAttributeMaxDynamicSharedMemorySize, GEMM_SMEM);
    cudaFuncSetAttribute(hgemm<false, true,  false, false>, cudaFuncAttributeMaxDynamicSharedMemorySize, GEMM_SMEM);

    const long nQKV = (long)BB * SS * DD;

    // 1: convert q/k/v to fp16 (one launch, grid.z = 3)
    {
        dim3 g(1024, 1, 3);
        f2h3_kernel<<<g, 256>>>(q, k, v, qh, kh, vh, nQKV / 4);
    }
    // 2: transpose+convert weights (one launch, grid.z = 3)
    {
        dim3 g(32, 32, 3), b(32, 8);
        wtrans3_kernel<<<g, b>>>(Wq, Wk, Wv, WqT, WkT, WvT);
    }

    const dim3 blk(128);

    // 3: Projections, batched into ONE launch (z selects q/k/v triple)
    {
        dim3 g(DD / 128, (BB * SS) / 128, 3);
        hgemm<true, false, true, true><<<g, blk, GEMM_SMEM>>>(
            qh, WqT, bq, Qp, DD, DD, DD, 1.0f, 0, 0, 0,
            kh, WkT, bk, Kp,
            vh, WvT, bv, Vp);
    }

    // 4: Scores (TN, f32 out): per batch M=N=2048, K=1024, alpha=1/32
    {
        dim3 g(SS / 128, SS / 128, BB);
        hgemm<false, false, false, false><<<g, blk, GEMM_SMEM>>>(
            Qp, Kp, nullptr, Sc, SS, DD, DD, 0.03125f,
            (long)SS * DD, (long)SS * DD, (long)SS * SS,
            nullptr, nullptr, nullptr, nullptr,
            nullptr, nullptr, nullptr, nullptr);
    }

    // 5: Softmax (f32 -> f16 probs)
    softmax2048_h<<<BB * SS, 256>>>(Sc, Ph);

    // 6: PV (NN, f32 out): A=Ph [S,S], B=Vp [S,D] k-major; M=2048, N=1024, K=2048
    {
        dim3 g(DD / 128, SS / 128, BB);
        hgemm<false, true, false, false><<<g, blk, GEMM_SMEM>>>(
            Ph, Vp, nullptr, out, DD, SS, DD, 1.0f,
            (long)SS * SS, (long)SS * DD, (long)SS * DD,
            nullptr, nullptr, nullptr, nullptr,
            nullptr, nullptr, nullptr, nullptr);
    }
}

// round 16
// speedup vs baseline: 1.1663x; 1.0111x over previous
#include <cuda_runtime.h>
#include <cuda_fp16.h>
#include <cstdint>
#include <math.h>

#define BB 4
#define SS 2048
#define DD 1024

// Scratch (__device__ globals — allocation-free rule). 16B-aligned for cp.async.
__device__ __align__(256) __half g_qh [(size_t)BB * SS * DD];
__device__ __align__(256) __half g_kh [(size_t)BB * SS * DD];
__device__ __align__(256) __half g_vh [(size_t)BB * SS * DD];
__device__ __align__(256) __half g_WqT[(size_t)DD * DD];
__device__ __align__(256) __half g_WkT[(size_t)DD * DD];
__device__ __align__(256) __half g_WvT[(size_t)DD * DD];
__device__ __align__(256) __half g_Qp [(size_t)BB * SS * DD];
__device__ __align__(256) __half g_Kp [(size_t)BB * SS * DD];
__device__ __align__(256) __half g_Vp [(size_t)BB * SS * DD];
__device__ __align__(256) float  g_Sc [(size_t)BB * SS * SS];
__device__ __align__(256) __half g_Ph [(size_t)BB * SS * SS];

// ---------------------------------------------------------------------------
// PTX helpers
// ---------------------------------------------------------------------------
__device__ __forceinline__ void cp16(uint32_t dst, const void* src) {
    asm volatile("cp.async.cg.shared.global [%0], [%1], 16;" :: "r"(dst), "l"(src));
}
__device__ __forceinline__ void cp_commit() {
    asm volatile("cp.async.commit_group;");
}
__device__ __forceinline__ void ldsm4(uint32_t* r, uint32_t addr) {
    asm volatile("ldmatrix.sync.aligned.m8n8.x4.shared.b16 {%0,%1,%2,%3}, [%4];"
        : "=r"(r[0]), "=r"(r[1]), "=r"(r[2]), "=r"(r[3]) : "r"(addr));
}
__device__ __forceinline__ void ldsm4t(uint32_t* r, uint32_t addr) {
    asm volatile("ldmatrix.sync.aligned.m8n8.x4.trans.shared.b16 {%0,%1,%2,%3}, [%4];"
        : "=r"(r[0]), "=r"(r[1]), "=r"(r[2]), "=r"(r[3]) : "r"(addr));
}
__device__ __forceinline__ void mma_f16(float* c, const uint32_t* a, const uint32_t* b) {
    asm volatile(
        "mma.sync.aligned.m16n8k16.row.col.f32.f16.f16.f32 "
        "{%0,%1,%2,%3}, {%4,%5,%6,%7}, {%8,%9}, {%0,%1,%2,%3};"
        : "+f"(c[0]), "+f"(c[1]), "+f"(c[2]), "+f"(c[3])
        : "r"(a[0]), "r"(a[1]), "r"(a[2]), "r"(a[3]), "r"(b[0]), "r"(b[1]));
}

// SW128 swizzle for 128B logical rows (A and TN-B tiles)
__device__ __forceinline__ uint32_t swz(uint32_t base, int row, int chunk) {
    return base + (uint32_t)(row * 128) + (uint32_t)((chunk ^ (row & 7)) << 4);
}
// Swizzle for 256B logical rows (NN B tile: 64 k-rows x 128 n-cols halves)
__device__ __forceinline__ uint32_t swzNN(uint32_t base, int row, int ch16) {
    return base + (uint32_t)(row * 256) + (uint32_t)((ch16 ^ ((row & 7) << 1)) << 4);
}

// ---------------------------------------------------------------------------
// FP16 tensor-core GEMM (proven R12 configuration).
//   TN (BNN=false): C[m,n] = alpha * sum_k A[m,k]*B[n,k] (+bias), B [N,K] row-major.
//   NN (BNN=true) : C[m,n] = alpha * sum_k A[m,k]*B[k,n],          B [K,N] row-major.
//   128 threads, CTA tile 128x128x64, 4 warps 64x64, 3-stage cp.async,
//   SW128 swizzle, fragment double-buffering.
//   PROJ3: blockIdx.z selects one of 3 (A,B,bias,C) sets; else z = batch.
// ---------------------------------------------------------------------------
#define STAGES 3
#define BK 64
#define TILE_BYTES 16384                    // A: 128x128B;  B(TN): 128x128B; B(NN): 64x256B
#define STAGE_BYTES (2 * TILE_BYTES)        // 32768
#define GEMM_SMEM (STAGES * STAGE_BYTES)    // 98304

template <bool PROJ3, bool BNN, bool HAS_BIAS, bool OUT_HALF>
__global__ __launch_bounds__(128, 2)
void hgemm(const __half* __restrict__ A, const __half* __restrict__ B,
           const float* __restrict__ bias, void* __restrict__ Cv,
           int N, int K, int ldB, float alpha, long sAz, long sBz, long sCz,
           const __half* __restrict__ A1, const __half* __restrict__ B1,
           const float* __restrict__ bias1, void* __restrict__ Cv1,
           const __half* __restrict__ A2, const __half* __restrict__ B2,
           const float* __restrict__ bias2, void* __restrict__ Cv2)
{
    extern __shared__ __align__(1024) char smraw[];
    const int tid  = threadIdx.x;
    const int lane = tid & 31;
    const int warp = tid >> 5;
    const int m0 = blockIdx.y * 128;
    const int n0 = blockIdx.x * 128;
    const int z  = blockIdx.z;

    const __half* Ab;
    const __half* Bb;
    const float*  biasb;
    void*         Cvb;
    if (PROJ3) {
        Ab    = (z == 0) ? A    : (z == 1) ? A1    : A2;
        Bb    = (z == 0) ? B    : (z == 1) ? B1    : B2;
        biasb = (z == 0) ? bias : (z == 1) ? bias1 : bias2;
        Cvb   = (z == 0) ? Cv   : (z == 1) ? Cv1   : Cv2;
    } else {
        Ab    = A + (long)z * sAz;
        Bb    = B + (long)z * sBz;
        biasb = bias;
        Cvb   = Cv;
    }

    const int wm = (warp >> 1) * 64;
    const int wn = (warp & 1) * 64;
    const int r  = lane >> 2;
    const int cc = lane & 3;

    const uint32_t smBase = (uint32_t)__cvta_generic_to_shared(smraw);

    // ldmatrix lane mapping
    const int aRow = lane & 15;
    const int aSub = lane >> 4;
    const int bRow = ((lane >> 4) << 3) + (lane & 7);             // TN
    const int bSub = (lane >> 3) & 1;                             // TN
    const int kLanePart = (((lane >> 3) & 1) << 3) + (lane & 7);  // NN
    const int nLanePart = (lane >> 4);                            // NN

    auto load_tiles = [&](int stage, int k0) {
        const uint32_t aS = smBase + (uint32_t)stage * STAGE_BYTES;
        const uint32_t bS = aS + TILE_BYTES;
#pragma unroll
        for (int i = 0; i < 8; i++) {
            const int c = tid + 128 * i;                  // 1024 x 16B chunks per tile
            {   // A tile: 128 m-rows x 128 B
                const int row   = c >> 3;
                const int chunk = c & 7;
                cp16(swz(aS, row, chunk), Ab + (long)(m0 + row) * K + k0 + chunk * 8);
            }
            if (BNN) {   // B tile: 64 k-rows x 256 B
                const int row  = c >> 4;
                const int ch16 = c & 15;
                cp16(swzNN(bS, row, ch16), Bb + (long)(k0 + row) * ldB + n0 + ch16 * 8);
            } else {     // B tile: 128 n-rows x 128 B
                const int row   = c >> 3;
                const int chunk = c & 7;
                cp16(swz(bS, row, chunk), Bb + (long)(n0 + row) * ldB + k0 + chunk * 8);
            }
        }
    };

    float acc[4][8][4];
#pragma unroll
    for (int mt = 0; mt < 4; mt++)
#pragma unroll
        for (int nt = 0; nt < 8; nt++)
#pragma unroll
            for (int i = 0; i < 4; i++) acc[mt][nt][i] = 0.0f;

    const int KT = K / BK;
    load_tiles(0, 0);      cp_commit();
    if (KT > 1) { load_tiles(1, BK); cp_commit(); }

    uint32_t afr[2][4][4], bfr[2][4][4];

    auto loadA = [&](uint32_t f[4][4], uint32_t aS, int ks) {
#pragma unroll
        for (int mt = 0; mt < 4; mt++)
            ldsm4(f[mt], swz(aS, wm + mt * 16 + aRow, ks * 2 + aSub));
    };
    auto loadB = [&](uint32_t f[4][4], uint32_t bS, int ks) {
        if (BNN) {
            const int kl = ks * 16 + kLanePart;
#pragma unroll
            for (int ng = 0; ng < 4; ng++) {
                const int nch = (wn >> 3) + ng * 2 + nLanePart;
                ldsm4t(f[ng], swzNN(bS, kl, nch));
            }
        } else {
#pragma unroll
            for (int ng = 0; ng < 4; ng++)
                ldsm4(f[ng], swz(bS, wn + ng * 16 + bRow, ks * 2 + bSub));
        }
    };

    for (int t = 0; t < KT; t++) {
        if (t + 2 < KT) asm volatile("cp.async.wait_group 1;");
        else            asm volatile("cp.async.wait_group 0;");
        __syncthreads();

        const int stage = t % STAGES;
        const uint32_t aS = smBase + (uint32_t)stage * STAGE_BYTES;
        const uint32_t bS = aS + TILE_BYTES;

        loadA(afr[0], aS, 0);
        loadB(bfr[0], bS, 0);

        if (t + 2 < KT) { load_tiles((t + 2) % STAGES, (t + 2) * BK); cp_commit(); }

#pragma unroll
        for (int ks = 0; ks < BK / 16; ks++) {
            const int cur = ks & 1;
            const int nxt = cur ^ 1;
            if (ks < BK / 16 - 1) {
                loadA(afr[nxt], aS, ks + 1);
                loadB(bfr[nxt], bS, ks + 1);
            }
#pragma unroll
            for (int mt = 0; mt < 4; mt++)
#pragma unroll
                for (int nt = 0; nt < 8; nt++)
                    mma_f16(acc[mt][nt], afr[cur][mt], &bfr[cur][nt >> 1][(nt & 1) * 2]);
        }
    }

    // epilogue
#pragma unroll
    for (int mt = 0; mt < 4; mt++) {
        const long row0 = m0 + wm + mt * 16 + r;
#pragma unroll
        for (int nt = 0; nt < 8; nt++) {
            const int colb = n0 + wn + nt * 8 + 2 * cc;
            float x0 = acc[mt][nt][0] * alpha;
            float x1 = acc[mt][nt][1] * alpha;
            float x2 = acc[mt][nt][2] * alpha;
            float x3 = acc[mt][nt][3] * alpha;
            if (HAS_BIAS) {
                const float b0 = biasb[colb], b1 = biasb[colb + 1];
                x0 += b0; x1 += b1; x2 += b0; x3 += b1;
            }
            if (OUT_HALF) {
                __half* Cb = (__half*)Cvb + (PROJ3 ? 0 : (long)z * sCz);
                *(__half2*)(Cb + row0 * N + colb)       = __floats2half2_rn(x0, x1);
                *(__half2*)(Cb + (row0 + 8) * N + colb) = __floats2half2_rn(x2, x3);
            } else {
                float* Cb = (float*)Cvb + (PROJ3 ? 0 : (long)z * sCz);
                *(float2*)(Cb + row0 * N + colb)       = make_float2(x0, x1);
                *(float2*)(Cb + (row0 + 8) * N + colb) = make_float2(x2, x3);
            }
        }
    }
}

// ---------------------------------------------------------------------------
// MIXED launch: scores tiles (blockIdx.x < 1024) + V-projection tiles (>= 1024)
// co-scheduled in one grid so V-proj warps fill scores-GEMM stall cycles.
// Both roles are TN with K = 1024; mainloop identical to the proven hgemm.
// ---------------------------------------------------------------------------
__global__ __launch_bounds__(128, 2)
void hgemm_mix(const __half* __restrict__ Qp, const __half* __restrict__ Kp,
               float* __restrict__ Sc,
               const __half* __restrict__ vh, const __half* __restrict__ WvT,
               const float* __restrict__ bv, __half* __restrict__ Vp)
{
    extern __shared__ __align__(1024) char smraw[];
    const int tid  = threadIdx.x;
    const int lane = tid & 31;
    const int warp = tid >> 5;

    const int bx = blockIdx.x;
    const bool isSc = (bx < 1024);
    const __half* Ab;
    const __half* Bb;
    const float*  biasb;
    float*  Cf = nullptr;
    __half* Ch = nullptr;
    int m0, n0, N;
    float alpha;
    if (isSc) {
        const int zb = bx >> 8;          // batch
        const int t  = bx & 255;         // 16x16 tiles per batch
        n0 = (t & 15) * 128;
        m0 = (t >> 4) * 128;
        Ab = Qp + (long)zb * SS * DD;
        Bb = Kp + (long)zb * SS * DD;
        Cf = Sc + (long)zb * SS * SS;
        biasb = nullptr;
        N = SS; alpha = 0.03125f;
    } else {
        const int i = bx - 1024;         // 8(n) x 64(m) tiles
        n0 = (i & 7) * 128;
        m0 = (i >> 3) * 128;
        Ab = vh; Bb = WvT; biasb = bv; Ch = Vp;
        N = DD; alpha = 1.0f;
    }
    const int K = DD;                    // 1024 for both roles

    const int wm = (warp >> 1) * 64;
    const int wn = (warp & 1) * 64;
    const int r  = lane >> 2;
    const int cc = lane & 3;

    const uint32_t smBase = (uint32_t)__cvta_generic_to_shared(smraw);

    const int aRow = lane & 15;
    const int aSub = lane >> 4;
    const int bRow = ((lane >> 4) << 3) + (lane & 7);
    const int bSub = (lane >> 3) & 1;

    auto load_tiles = [&](int stage, int k0) {
        const uint32_t aS = smBase + (uint32_t)stage * STAGE_BYTES;
        const uint32_t bS = aS + TILE_BYTES;
#pragma unroll
        for (int i = 0; i < 8; i++) {
            const int c = tid + 128 * i;
            const int row   = c >> 3;
            const int chunk = c & 7;
            cp16(swz(aS, row, chunk), Ab + (long)(m0 + row) * K + k0 + chunk * 8);
            cp16(swz(bS, row, chunk), Bb + (long)(n0 + row) * K + k0 + chunk * 8);
        }
    };

    float acc[4][8][4];
#pragma unroll
    for (int mt = 0; mt < 4; mt++)
#pragma unroll
        for (int nt = 0; nt < 8; nt++)
#pragma unroll
            for (int i = 0; i < 4; i++) acc[mt][nt][i] = 0.0f;

    const int KT = K / BK;               // 16
    load_tiles(0, 0);  cp_commit();
    load_tiles(1, BK); cp_commit();

    uint32_t afr[2][4][4], bfr[2][4][4];

    auto loadA = [&](uint32_t f[4][4], uint32_t aS, int ks) {
#pragma unroll
        for (int mt = 0; mt < 4; mt++)
            ldsm4(f[mt], swz(aS, wm + mt * 16 + aRow, ks * 2 + aSub));
    };
    auto loadB = [&](uint32_t f[4][4], uint32_t bS, int ks) {
#pragma unroll
        for (int ng = 0; ng < 4; ng++)
            ldsm4(f[ng], swz(bS, wn + ng * 16 + bRow, ks * 2 + bSub));
    };

    for (int t = 0; t < KT; t++) {
        if (t + 2 < KT) asm volatile("cp.async.wait_group 1;");
        else            asm volatile("cp.async.wait_group 0;");
        __syncthreads();

        const int stage = t % STAGES;
        const uint32_t aS = smBase + (uint32_t)stage * STAGE_BYTES;
        const uint32_t bS = aS + TILE_BYTES;

        loadA(afr[0], aS, 0);
        loadB(bfr[0], bS, 0);

        if (t + 2 < KT) { load_tiles((t + 2) % STAGES, (t + 2) * BK); cp_commit(); }

#pragma unroll
        for (int ks = 0; ks < BK / 16; ks++) {
            const int cur = ks & 1;
            const int nxt = cur ^ 1;
            if (ks < BK / 16 - 1) {
                loadA(afr[nxt], aS, ks + 1);
                loadB(bfr[nxt], bS, ks + 1);
            }
#pragma unroll
            for (int mt = 0; mt < 4; mt++)
#pragma unroll
                for (int nt = 0; nt < 8; nt++)
                    mma_f16(acc[mt][nt], afr[cur][mt], &bfr[cur][nt >> 1][(nt & 1) * 2]);
        }
    }

    // epilogue (role-uniform branch)
#pragma unroll
    for (int mt = 0; mt < 4; mt++) {
        const long row0 = m0 + wm + mt * 16 + r;
#pragma unroll
        for (int nt = 0; nt < 8; nt++) {
            const int colb = n0 + wn + nt * 8 + 2 * cc;
            float x0 = acc[mt][nt][0] * alpha;
            float x1 = acc[mt][nt][1] * alpha;
            float x2 = acc[mt][nt][2] * alpha;
            float x3 = acc[mt][nt][3] * alpha;
            if (isSc) {
                *(float2*)(Cf + row0 * N + colb)       = make_float2(x0, x1);
                *(float2*)(Cf + (row0 + 8) * N + colb) = make_float2(x2, x3);
            } else {
                const float b0 = biasb[colb], b1 = biasb[colb + 1];
                x0 += b0; x1 += b1; x2 += b0; x3 += b1;
                *(__half2*)(Ch + row0 * N + colb)       = __floats2half2_rn(x0, x1);
                *(__half2*)(Ch + (row0 + 8) * N + colb) = __floats2half2_rn(x2, x3);
            }
        }
    }
}

// ---------------------------------------------------------------------------
// Batched fp32 -> fp16(rn): z selects which of 3 arrays
// ---------------------------------------------------------------------------
__global__ __launch_bounds__(256)
void f2h3_kernel(const float* __restrict__ a0, const float* __restrict__ a1,
                 const float* __restrict__ a2, __half* __restrict__ o0,
                 __half* __restrict__ o1, __half* __restrict__ o2, long n4)
{
    const float* in = (blockIdx.z == 0) ? a0 : (blockIdx.z == 1) ? a1 : a2;
    __half* out     = (blockIdx.z == 0) ? o0 : (blockIdx.z == 1) ? o1 : o2;
    long i = (long)blockIdx.x * blockDim.x + threadIdx.x;
    const long stride = (long)gridDim.x * blockDim.x;
    for (; i < n4; i += stride) {
        float4 v = ((const float4*)in)[i];
        __half2* o = (__half2*)(out + i * 4);
        o[0] = __floats2half2_rn(v.x, v.y);
        o[1] = __floats2half2_rn(v.z, v.w);
    }
}

// ---------------------------------------------------------------------------
// Batched transpose + convert: W f32 [K][N] -> half [N][K] (z selects weight)
// ---------------------------------------------------------------------------
__global__ __launch_bounds__(256)
void wtrans3_kernel(const float* __restrict__ a0, const float* __restrict__ a1,
                    const float* __restrict__ a2, __half* __restrict__ o0,
                    __half* __restrict__ o1, __half* __restrict__ o2)
{
    const float* in = (blockIdx.z == 0) ? a0 : (blockIdx.z == 1) ? a1 : a2;
    __half* out     = (blockIdx.z == 0) ? o0 : (blockIdx.z == 1) ? o1 : o2;
    __shared__ float t[32][33];
    const int bx = blockIdx.x * 32;   // n
    const int by = blockIdx.y * 32;   // k
    const int tx = threadIdx.x, ty = threadIdx.y;
#pragma unroll
    for (int i = ty; i < 32; i += 8)
        t[i][tx] = in[(long)(by + i) * DD + bx + tx];
    __syncthreads();
#pragma unroll
    for (int i = ty; i < 32; i += 8)
        out[(long)(bx + i) * DD + by + tx] = __float2half_rn(t[tx][i]);
}

// ---------------------------------------------------------------------------
// Row softmax over 2048 fp32 cols -> fp16 probabilities (vectorized)
// ---------------------------------------------------------------------------
__global__ __launch_bounds__(256)
void softmax2048_h(const float* __restrict__ S, __half* __restrict__ P)
{
    const float4* row = (const float4*)(S + (long)blockIdx.x * SS);
    uint2*        po  = (uint2*)(P + (long)blockIdx.x * SS);
    const int t = threadIdx.x;

    float4 v4[2];
    float v[8];
    float mx = -1e30f;
#pragma unroll
    for (int i = 0; i < 2; i++) {
        v4[i] = row[t + i * 256];
        v[i*4+0] = v4[i].x; v[i*4+1] = v4[i].y; v[i*4+2] = v4[i].z; v[i*4+3] = v4[i].w;
    }
#pragma unroll
    for (int i = 0; i < 8; i++) mx = fmaxf(mx, v[i]);
#pragma unroll
    for (int o = 16; o > 0; o >>= 1)
        mx = fmaxf(mx, __shfl_xor_sync(0xFFFFFFFFu, mx, o));

    __shared__ float red[8];
    if ((t & 31) == 0) red[t >> 5] = mx;
    __syncthreads();
    float bmax = red[0];
#pragma unroll
    for (int i = 1; i < 8; i++) bmax = fmaxf(bmax, red[i]);
    __syncthreads();

    float sum = 0.0f;
#pragma unroll
    for (int i = 0; i < 8; i++) {
        v[i] = __expf(v[i] - bmax);
        sum += v[i];
    }
#pragma unroll
    for (int o = 16; o > 0; o >>= 1)
        sum += __shfl_xor_sync(0xFFFFFFFFu, sum, o);
    if ((t & 31) == 0) red[t >> 5] = sum;
    __syncthreads();
    float tot = 0.0f;
#pragma unroll
    for (int i = 0; i < 8; i++) tot += red[i];

    const float inv = __frcp_rn(tot);
#pragma unroll
    for (int i = 0; i < 2; i++) {
        __half2 h0 = __floats2half2_rn(v[i*4+0] * inv, v[i*4+1] * inv);
        __half2 h1 = __floats2half2_rn(v[i*4+2] * inv, v[i*4+3] * inv);
        uint2 u;
        u.x = *(uint32_t*)&h0;
        u.y = *(uint32_t*)&h1;
        po[t + i * 256] = u;
    }
}

// ---------------------------------------------------------------------------
extern "C" void kernel_launch(void* const* d_in, const int* in_sizes, int n_in,
                              void* d_out, int out_size)
{
    const float* q  = (const float*)d_in[0];
    const float* k  = (const float*)d_in[1];
    const float* v  = (const float*)d_in[2];
    const float* Wq = (const float*)d_in[3];
    const float* bq = (const float*)d_in[4];
    const float* Wk = (const float*)d_in[5];
    const float* bk = (const float*)d_in[6];
    const float* Wv = (const float*)d_in[7];
    const float* bv = (const float*)d_in[8];
    float* out = (float*)d_out;

    __half *qh, *kh, *vh, *WqT, *WkT, *WvT, *Qp, *Kp, *Vp, *Ph;
    float *Sc;
    cudaGetSymbolAddress((void**)&qh,  g_qh);
    cudaGetSymbolAddress((void**)&kh,  g_kh);
    cudaGetSymbolAddress((void**)&vh,  g_vh);
    cudaGetSymbolAddress((void**)&WqT, g_WqT);
    cudaGetSymbolAddress((void**)&WkT, g_WkT);
    cudaGetSymbolAddress((void**)&WvT, g_WvT);
    cudaGetSymbolAddress((void**)&Qp,  g_Qp);
    cudaGetSymbolAddress((void**)&Kp,  g_Kp);
    cudaGetSymbolAddress((void**)&Vp,  g_Vp);
    cudaGetSymbolAddress((void**)&Sc,  g_Sc);
    cudaGetSymbolAddress((void**)&Ph,  g_Ph);

    cudaFuncSetAttribute(hgemm<true,  false, true,  true >, cudaFuncAttributeMaxDynamicSharedMemorySize, GEMM_SMEM);
    cudaFuncSetAttribute(hgemm<false, true,  false, false>, cudaFuncAttributeMaxDynamicSharedMemorySize, GEMM_SMEM);
    cudaFuncSetAttribute(hgemm_mix, cudaFuncAttributeMaxDynamicSharedMemorySize, GEMM_SMEM);

    const long nQKV = (long)BB * SS * DD;

    // 1: convert q/k/v to fp16 (one launch, grid.z = 3)
    {
        dim3 g(1024, 1, 3);
        f2h3_kernel<<<g, 256>>>(q, k, v, qh, kh, vh, nQKV / 4);
    }
    // 2: transpose+convert weights (one launch, grid.z = 3)
    {
        dim3 g(32, 32, 3), b(32, 8);
        wtrans3_kernel<<<g, b>>>(Wq, Wk, Wv, WqT, WkT, WvT);
    }

    const dim3 blk(128);

    // 3: Q and K projections only (z in {0,1} selects triple)
    {
        dim3 g(DD / 128, (BB * SS) / 128, 2);
        hgemm<true, false, true, true><<<g, blk, GEMM_SMEM>>>(
            qh, WqT, bq, Qp, DD, DD, DD, 1.0f, 0, 0, 0,
            kh, WkT, bk, Kp,
            nullptr, nullptr, nullptr, nullptr);
    }

    // 4: MIXED: scores (1024 CTAs) + V-projection (512 CTAs) in ONE launch —
    //    V-proj warps fill scores-GEMM stall cycles.
    {
        hgemm_mix<<<1536, blk, GEMM_SMEM>>>(Qp, Kp, Sc, vh, WvT, bv, Vp);
    }

    // 5: Softmax (f32 -> f16 probs)
    softmax2048_h<<<BB * SS, 256>>>(Sc, Ph);

    // 6: PV (NN, f32 out): A=Ph [S,S], B=Vp [S,D] k-major; M=2048, N=1024, K=2048
    {
        dim3 g(DD / 128, SS / 128, BB);
        hgemm<false, true, false, false><<<g, blk, GEMM_SMEM>>>(
            Ph, Vp, nullptr, out, DD, SS, DD, 1.0f,
            (long)SS * SS, (long)SS * DD, (long)SS * DD,
            nullptr, nullptr, nullptr, nullptr,
            nullptr, nullptr, nullptr, nullptr);
    }
}

// round 17
// speedup vs baseline: 1.2000x; 1.0289x over previous
#include <cuda_runtime.h>
#include <cuda_fp16.h>
#include <cstdint>
#include <math.h>

#define BB 4
#define SS 2048
#define DD 1024

// Scratch (__device__ globals — allocation-free rule). 16B-aligned for cp.async.
__device__ __align__(256) __half g_qh [(size_t)BB * SS * DD];
__device__ __align__(256) __half g_kh [(size_t)BB * SS * DD];
__device__ __align__(256) __half g_vh [(size_t)BB * SS * DD];
__device__ __align__(256) __half g_WqT[(size_t)DD * DD];
__device__ __align__(256) __half g_WkT[(size_t)DD * DD];
__device__ __align__(256) __half g_WvT[(size_t)DD * DD];
__device__ __align__(256) __half g_Qp [(size_t)BB * SS * DD];
__device__ __align__(256) __half g_Kp [(size_t)BB * SS * DD];
__device__ __align__(256) __half g_Vp [(size_t)BB * SS * DD];
__device__ __align__(256) __half g_Sch[(size_t)BB * SS * SS];   // scores, fp16
__device__ __align__(256) __half g_Ph [(size_t)BB * SS * SS];   // probs, fp16

// ---------------------------------------------------------------------------
// PTX helpers
// ---------------------------------------------------------------------------
__device__ __forceinline__ void cp16(uint32_t dst, const void* src) {
    asm volatile("cp.async.cg.shared.global [%0], [%1], 16;" :: "r"(dst), "l"(src));
}
__device__ __forceinline__ void cp_commit() {
    asm volatile("cp.async.commit_group;");
}
__device__ __forceinline__ void ldsm4(uint32_t* r, uint32_t addr) {
    asm volatile("ldmatrix.sync.aligned.m8n8.x4.shared.b16 {%0,%1,%2,%3}, [%4];"
        : "=r"(r[0]), "=r"(r[1]), "=r"(r[2]), "=r"(r[3]) : "r"(addr));
}
__device__ __forceinline__ void ldsm4t(uint32_t* r, uint32_t addr) {
    asm volatile("ldmatrix.sync.aligned.m8n8.x4.trans.shared.b16 {%0,%1,%2,%3}, [%4];"
        : "=r"(r[0]), "=r"(r[1]), "=r"(r[2]), "=r"(r[3]) : "r"(addr));
}
__device__ __forceinline__ void mma_f16(float* c, const uint32_t* a, const uint32_t* b) {
    asm volatile(
        "mma.sync.aligned.m16n8k16.row.col.f32.f16.f16.f32 "
        "{%0,%1,%2,%3}, {%4,%5,%6,%7}, {%8,%9}, {%0,%1,%2,%3};"
        : "+f"(c[0]), "+f"(c[1]), "+f"(c[2]), "+f"(c[3])
        : "r"(a[0]), "r"(a[1]), "r"(a[2]), "r"(a[3]), "r"(b[0]), "r"(b[1]));
}

// SW128 swizzle for 128B logical rows (A and TN-B tiles)
__device__ __forceinline__ uint32_t swz(uint32_t base, int row, int chunk) {
    return base + (uint32_t)(row * 128) + (uint32_t)((chunk ^ (row & 7)) << 4);
}
// Swizzle for 256B logical rows (NN B tile: 64 k-rows x 128 n-cols halves)
__device__ __forceinline__ uint32_t swzNN(uint32_t base, int row, int ch16) {
    return base + (uint32_t)(row * 256) + (uint32_t)((ch16 ^ ((row & 7) << 1)) << 4);
}

// ---------------------------------------------------------------------------
// FP16 tensor-core GEMM (proven R12 configuration).
//   TN (BNN=false): C[m,n] = alpha * sum_k A[m,k]*B[n,k] (+bias), B [N,K] row-major.
//   NN (BNN=true) : C[m,n] = alpha * sum_k A[m,k]*B[k,n],          B [K,N] row-major.
//   128 threads, CTA tile 128x128x64, 4 warps 64x64, 3-stage cp.async,
//   SW128 swizzle, fragment double-buffering.
//   PROJ3: blockIdx.z selects one of 3 (A,B,bias,C) sets; else z = batch.
// ---------------------------------------------------------------------------
#define STAGES 3
#define BK 64
#define TILE_BYTES 16384                    // A: 128x128B;  B(TN): 128x128B; B(NN): 64x256B
#define STAGE_BYTES (2 * TILE_BYTES)        // 32768
#define GEMM_SMEM (STAGES * STAGE_BYTES)    // 98304

template <bool PROJ3, bool BNN, bool HAS_BIAS, bool OUT_HALF>
__global__ __launch_bounds__(128, 2)
void hgemm(const __half* __restrict__ A, const __half* __restrict__ B,
           const float* __restrict__ bias, void* __restrict__ Cv,
           int N, int K, int ldB, float alpha, long sAz, long sBz, long sCz,
           const __half* __restrict__ A1, const __half* __restrict__ B1,
           const float* __restrict__ bias1, void* __restrict__ Cv1,
           const __half* __restrict__ A2, const __half* __restrict__ B2,
           const float* __restrict__ bias2, void* __restrict__ Cv2)
{
    extern __shared__ __align__(1024) char smraw[];
    const int tid  = threadIdx.x;
    const int lane = tid & 31;
    const int warp = tid >> 5;
    const int m0 = blockIdx.y * 128;
    const int n0 = blockIdx.x * 128;
    const int z  = blockIdx.z;

    const __half* Ab;
    const __half* Bb;
    const float*  biasb;
    void*         Cvb;
    if (PROJ3) {
        Ab    = (z == 0) ? A    : (z == 1) ? A1    : A2;
        Bb    = (z == 0) ? B    : (z == 1) ? B1    : B2;
        biasb = (z == 0) ? bias : (z == 1) ? bias1 : bias2;
        Cvb   = (z == 0) ? Cv   : (z == 1) ? Cv1   : Cv2;
    } else {
        Ab    = A + (long)z * sAz;
        Bb    = B + (long)z * sBz;
        biasb = bias;
        Cvb   = Cv;
    }

    const int wm = (warp >> 1) * 64;
    const int wn = (warp & 1) * 64;
    const int r  = lane >> 2;
    const int cc = lane & 3;

    const uint32_t smBase = (uint32_t)__cvta_generic_to_shared(smraw);

    const int aRow = lane & 15;
    const int aSub = lane >> 4;
    const int bRow = ((lane >> 4) << 3) + (lane & 7);             // TN
    const int bSub = (lane >> 3) & 1;                             // TN
    const int kLanePart = (((lane >> 3) & 1) << 3) + (lane & 7);  // NN
    const int nLanePart = (lane >> 4);                            // NN

    auto load_tiles = [&](int stage, int k0) {
        const uint32_t aS = smBase + (uint32_t)stage * STAGE_BYTES;
        const uint32_t bS = aS + TILE_BYTES;
#pragma unroll
        for (int i = 0; i < 8; i++) {
            const int c = tid + 128 * i;
            {   // A tile: 128 m-rows x 128 B
                const int row   = c >> 3;
                const int chunk = c & 7;
                cp16(swz(aS, row, chunk), Ab + (long)(m0 + row) * K + k0 + chunk * 8);
            }
            if (BNN) {   // B tile: 64 k-rows x 256 B
                const int row  = c >> 4;
                const int ch16 = c & 15;
                cp16(swzNN(bS, row, ch16), Bb + (long)(k0 + row) * ldB + n0 + ch16 * 8);
            } else {     // B tile: 128 n-rows x 128 B
                const int row   = c >> 3;
                const int chunk = c & 7;
                cp16(swz(bS, row, chunk), Bb + (long)(n0 + row) * ldB + k0 + chunk * 8);
            }
        }
    };

    float acc[4][8][4];
#pragma unroll
    for (int mt = 0; mt < 4; mt++)
#pragma unroll
        for (int nt = 0; nt < 8; nt++)
#pragma unroll
            for (int i = 0; i < 4; i++) acc[mt][nt][i] = 0.0f;

    const int KT = K / BK;
    load_tiles(0, 0);      cp_commit();
    if (KT > 1) { load_tiles(1, BK); cp_commit(); }

    uint32_t afr[2][4][4], bfr[2][4][4];

    auto loadA = [&](uint32_t f[4][4], uint32_t aS, int ks) {
#pragma unroll
        for (int mt = 0; mt < 4; mt++)
            ldsm4(f[mt], swz(aS, wm + mt * 16 + aRow, ks * 2 + aSub));
    };
    auto loadB = [&](uint32_t f[4][4], uint32_t bS, int ks) {
        if (BNN) {
            const int kl = ks * 16 + kLanePart;
#pragma unroll
            for (int ng = 0; ng < 4; ng++) {
                const int nch = (wn >> 3) + ng * 2 + nLanePart;
                ldsm4t(f[ng], swzNN(bS, kl, nch));
            }
        } else {
#pragma unroll
            for (int ng = 0; ng < 4; ng++)
                ldsm4(f[ng], swz(bS, wn + ng * 16 + bRow, ks * 2 + bSub));
        }
    };

    for (int t = 0; t < KT; t++) {
        if (t + 2 < KT) asm volatile("cp.async.wait_group 1;");
        else            asm volatile("cp.async.wait_group 0;");
        __syncthreads();

        const int stage = t % STAGES;
        const uint32_t aS = smBase + (uint32_t)stage * STAGE_BYTES;
        const uint32_t bS = aS + TILE_BYTES;

        loadA(afr[0], aS, 0);
        loadB(bfr[0], bS, 0);

        if (t + 2 < KT) { load_tiles((t + 2) % STAGES, (t + 2) * BK); cp_commit(); }

#pragma unroll
        for (int ks = 0; ks < BK / 16; ks++) {
            const int cur = ks & 1;
            const int nxt = cur ^ 1;
            if (ks < BK / 16 - 1) {
                loadA(afr[nxt], aS, ks + 1);
                loadB(bfr[nxt], bS, ks + 1);
            }
#pragma unroll
            for (int mt = 0; mt < 4; mt++)
#pragma unroll
                for (int nt = 0; nt < 8; nt++)
                    mma_f16(acc[mt][nt], afr[cur][mt], &bfr[cur][nt >> 1][(nt & 1) * 2]);
        }
    }

    // epilogue
#pragma unroll
    for (int mt = 0; mt < 4; mt++) {
        const long row0 = m0 + wm + mt * 16 + r;
#pragma unroll
        for (int nt = 0; nt < 8; nt++) {
            const int colb = n0 + wn + nt * 8 + 2 * cc;
            float x0 = acc[mt][nt][0] * alpha;
            float x1 = acc[mt][nt][1] * alpha;
            float x2 = acc[mt][nt][2] * alpha;
            float x3 = acc[mt][nt][3] * alpha;
            if (HAS_BIAS) {
                const float b0 = biasb[colb], b1 = biasb[colb + 1];
                x0 += b0; x1 += b1; x2 += b0; x3 += b1;
            }
            if (OUT_HALF) {
                __half* Cb = (__half*)Cvb + (PROJ3 ? 0 : (long)z * sCz);
                *(__half2*)(Cb + row0 * N + colb)       = __floats2half2_rn(x0, x1);
                *(__half2*)(Cb + (row0 + 8) * N + colb) = __floats2half2_rn(x2, x3);
            } else {
                float* Cb = (float*)Cvb + (PROJ3 ? 0 : (long)z * sCz);
                *(float2*)(Cb + row0 * N + colb)       = make_float2(x0, x1);
                *(float2*)(Cb + (row0 + 8) * N + colb) = make_float2(x2, x3);
            }
        }
    }
}

// ---------------------------------------------------------------------------
// MIXED launch: scores tiles (blockIdx.x < 1024, fp16 out) + V-projection
// tiles (>= 1024) co-scheduled so V-proj warps fill scores-GEMM stalls.
// ---------------------------------------------------------------------------
__global__ __launch_bounds__(128, 2)
void hgemm_mix(const __half* __restrict__ Qp, const __half* __restrict__ Kp,
               __half* __restrict__ Sch,
               const __half* __restrict__ vh, const __half* __restrict__ WvT,
               const float* __restrict__ bv, __half* __restrict__ Vp)
{
    extern __shared__ __align__(1024) char smraw[];
    const int tid  = threadIdx.x;
    const int lane = tid & 31;
    const int warp = tid >> 5;

    const int bx = blockIdx.x;
    const bool isSc = (bx < 1024);
    const __half* Ab;
    const __half* Bb;
    const float*  biasb;
    __half* Ch;
    int m0, n0, N;
    float alpha;
    if (isSc) {
        const int zb = bx >> 8;
        const int t  = bx & 255;
        n0 = (t & 15) * 128;
        m0 = (t >> 4) * 128;
        Ab = Qp + (long)zb * SS * DD;
        Bb = Kp + (long)zb * SS * DD;
        Ch = Sch + (long)zb * SS * SS;
        biasb = nullptr;
        N = SS; alpha = 0.03125f;
    } else {
        const int i = bx - 1024;
        n0 = (i & 7) * 128;
        m0 = (i >> 3) * 128;
        Ab = vh; Bb = WvT; biasb = bv; Ch = Vp;
        N = DD; alpha = 1.0f;
    }
    const int K = DD;

    const int wm = (warp >> 1) * 64;
    const int wn = (warp & 1) * 64;
    const int r  = lane >> 2;
    const int cc = lane & 3;

    const uint32_t smBase = (uint32_t)__cvta_generic_to_shared(smraw);

    const int aRow = lane & 15;
    const int aSub = lane >> 4;
    const int bRow = ((lane >> 4) << 3) + (lane & 7);
    const int bSub = (lane >> 3) & 1;

    auto load_tiles = [&](int stage, int k0) {
        const uint32_t aS = smBase + (uint32_t)stage * STAGE_BYTES;
        const uint32_t bS = aS + TILE_BYTES;
#pragma unroll
        for (int i = 0; i < 8; i++) {
            const int c = tid + 128 * i;
            const int row   = c >> 3;
            const int chunk = c & 7;
            cp16(swz(aS, row, chunk), Ab + (long)(m0 + row) * K + k0 + chunk * 8);
            cp16(swz(bS, row, chunk), Bb + (long)(n0 + row) * K + k0 + chunk * 8);
        }
    };

    float acc[4][8][4];
#pragma unroll
    for (int mt = 0; mt < 4; mt++)
#pragma unroll
        for (int nt = 0; nt < 8; nt++)
#pragma unroll
            for (int i = 0; i < 4; i++) acc[mt][nt][i] = 0.0f;

    const int KT = K / BK;               // 16
    load_tiles(0, 0);  cp_commit();
    load_tiles(1, BK); cp_commit();

    uint32_t afr[2][4][4], bfr[2][4][4];

    auto loadA = [&](uint32_t f[4][4], uint32_t aS, int ks) {
#pragma unroll
        for (int mt = 0; mt < 4; mt++)
            ldsm4(f[mt], swz(aS, wm + mt * 16 + aRow, ks * 2 + aSub));
    };
    auto loadB = [&](uint32_t f[4][4], uint32_t bS, int ks) {
#pragma unroll
        for (int ng = 0; ng < 4; ng++)
            ldsm4(f[ng], swz(bS, wn + ng * 16 + bRow, ks * 2 + bSub));
    };

    for (int t = 0; t < KT; t++) {
        if (t + 2 < KT) asm volatile("cp.async.wait_group 1;");
        else            asm volatile("cp.async.wait_group 0;");
        __syncthreads();

        const int stage = t % STAGES;
        const uint32_t aS = smBase + (uint32_t)stage * STAGE_BYTES;
        const uint32_t bS = aS + TILE_BYTES;

        loadA(afr[0], aS, 0);
        loadB(bfr[0], bS, 0);

        if (t + 2 < KT) { load_tiles((t + 2) % STAGES, (t + 2) * BK); cp_commit(); }

#pragma unroll
        for (int ks = 0; ks < BK / 16; ks++) {
            const int cur = ks & 1;
            const int nxt = cur ^ 1;
            if (ks < BK / 16 - 1) {
                loadA(afr[nxt], aS, ks + 1);
                loadB(bfr[nxt], bS, ks + 1);
            }
#pragma unroll
            for (int mt = 0; mt < 4; mt++)
#pragma unroll
                for (int nt = 0; nt < 8; nt++)
                    mma_f16(acc[mt][nt], afr[cur][mt], &bfr[cur][nt >> 1][(nt & 1) * 2]);
        }
    }

    // epilogue (both roles write fp16)
#pragma unroll
    for (int mt = 0; mt < 4; mt++) {
        const long row0 = m0 + wm + mt * 16 + r;
#pragma unroll
        for (int nt = 0; nt < 8; nt++) {
            const int colb = n0 + wn + nt * 8 + 2 * cc;
            float x0 = acc[mt][nt][0] * alpha;
            float x1 = acc[mt][nt][1] * alpha;
            float x2 = acc[mt][nt][2] * alpha;
            float x3 = acc[mt][nt][3] * alpha;
            if (!isSc) {
                const float b0 = biasb[colb], b1 = biasb[colb + 1];
                x0 += b0; x1 += b1; x2 += b0; x3 += b1;
            }
            *(__half2*)(Ch + row0 * N + colb)       = __floats2half2_rn(x0, x1);
            *(__half2*)(Ch + (row0 + 8) * N + colb) = __floats2half2_rn(x2, x3);
        }
    }
}

// ---------------------------------------------------------------------------
// Combined prep: z in [0,3) = fp32->fp16 convert of q/k/v;
//                z in [3,6) = transpose+convert of Wq/Wk/Wv.
// ---------------------------------------------------------------------------
__global__ __launch_bounds__(256)
void prep_kernel(const float* __restrict__ q, const float* __restrict__ k,
                 const float* __restrict__ v,
                 __half* __restrict__ qh, __half* __restrict__ kh,
                 __half* __restrict__ vh,
                 const float* __restrict__ Wq, const float* __restrict__ Wk,
                 const float* __restrict__ Wv,
                 __half* __restrict__ WqT, __half* __restrict__ WkT,
                 __half* __restrict__ WvT, long n4)
{
    __shared__ float t[32][33];
    const int z = blockIdx.z;
    const int tid = threadIdx.x;
    if (z < 3) {
        const float* in = (z == 0) ? q : (z == 1) ? k : v;
        __half* out     = (z == 0) ? qh : (z == 1) ? kh : vh;
        long i = (long)blockIdx.x * 256 + tid;
        const long stride = (long)gridDim.x * 256;
        for (; i < n4; i += stride) {
            float4 vv = ((const float4*)in)[i];
            __half2* o = (__half2*)(out + i * 4);
            o[0] = __floats2half2_rn(vv.x, vv.y);
            o[1] = __floats2half2_rn(vv.z, vv.w);
        }
    } else {
        const float* in = (z == 3) ? Wq : (z == 4) ? Wk : Wv;
        __half* out     = (z == 3) ? WqT : (z == 4) ? WkT : WvT;
        const int tile = blockIdx.x;           // 0..1023
        const int bx = (tile & 31) * 32;       // n
        const int by = (tile >> 5) * 32;       // k
        const int tx = tid & 31, ty = tid >> 5;
#pragma unroll
        for (int i = ty; i < 32; i += 8)
            t[i][tx] = in[(long)(by + i) * DD + bx + tx];
        __syncthreads();
#pragma unroll
        for (int i = ty; i < 32; i += 8)
            out[(long)(bx + i) * DD + by + tx] = __float2half_rn(t[tx][i]);
    }
}

// ---------------------------------------------------------------------------
// Row softmax over 2048 fp16 scores -> fp16 probabilities.
// Each thread owns 8 contiguous halves (one uint4 load / one uint4 store).
// ---------------------------------------------------------------------------
__global__ __launch_bounds__(256)
void softmax2048_h(const __half* __restrict__ S, __half* __restrict__ P)
{
    const uint4* row = (const uint4*)(S + (long)blockIdx.x * SS);
    uint4*       po  = (uint4*)(P + (long)blockIdx.x * SS);
    const int t = threadIdx.x;

    uint4 u = row[t];
    float v[8];
    {
        __half2 h;
        h = *(__half2*)&u.x; v[0] = __low2float(h);  v[1] = __high2float(h);
        h = *(__half2*)&u.y; v[2] = __low2float(h);  v[3] = __high2float(h);
        h = *(__half2*)&u.z; v[4] = __low2float(h);  v[5] = __high2float(h);
        h = *(__half2*)&u.w; v[6] = __low2float(h);  v[7] = __high2float(h);
    }

    float mx = v[0];
#pragma unroll
    for (int i = 1; i < 8; i++) mx = fmaxf(mx, v[i]);
#pragma unroll
    for (int o = 16; o > 0; o >>= 1)
        mx = fmaxf(mx, __shfl_xor_sync(0xFFFFFFFFu, mx, o));

    __shared__ float red[8];
    if ((t & 31) == 0) red[t >> 5] = mx;
    __syncthreads();
    float bmax = red[0];
#pragma unroll
    for (int i = 1; i < 8; i++) bmax = fmaxf(bmax, red[i]);
    __syncthreads();

    float sum = 0.0f;
#pragma unroll
    for (int i = 0; i < 8; i++) {
        v[i] = __expf(v[i] - bmax);
        sum += v[i];
    }
#pragma unroll
    for (int o = 16; o > 0; o >>= 1)
        sum += __shfl_xor_sync(0xFFFFFFFFu, sum, o);
    if ((t & 31) == 0) red[t >> 5] = sum;
    __syncthreads();
    float tot = 0.0f;
#pragma unroll
    for (int i = 0; i < 8; i++) tot += red[i];

    const float inv = __frcp_rn(tot);
    uint4 o;
    __half2 h0 = __floats2half2_rn(v[0] * inv, v[1] * inv);
    __half2 h1 = __floats2half2_rn(v[2] * inv, v[3] * inv);
    __half2 h2 = __floats2half2_rn(v[4] * inv, v[5] * inv);
    __half2 h3 = __floats2half2_rn(v[6] * inv, v[7] * inv);
    o.x = *(uint32_t*)&h0; o.y = *(uint32_t*)&h1;
    o.z = *(uint32_t*)&h2; o.w = *(uint32_t*)&h3;
    po[t] = o;
}

// ---------------------------------------------------------------------------
extern "C" void kernel_launch(void* const* d_in, const int* in_sizes, int n_in,
                              void* d_out, int out_size)
{
    const float* q  = (const float*)d_in[0];
    const float* k  = (const float*)d_in[1];
    const float* v  = (const float*)d_in[2];
    const float* Wq = (const float*)d_in[3];
    const float* bq = (const float*)d_in[4];
    const float* Wk = (const float*)d_in[5];
    const float* bk = (const float*)d_in[6];
    const float* Wv = (const float*)d_in[7];
    const float* bv = (const float*)d_in[8];
    float* out = (float*)d_out;

    __half *qh, *kh, *vh, *WqT, *WkT, *WvT, *Qp, *Kp, *Vp, *Sch, *Ph;
    cudaGetSymbolAddress((void**)&qh,  g_qh);
    cudaGetSymbolAddress((void**)&kh,  g_kh);
    cudaGetSymbolAddress((void**)&vh,  g_vh);
    cudaGetSymbolAddress((void**)&WqT, g_WqT);
    cudaGetSymbolAddress((void**)&WkT, g_WkT);
    cudaGetSymbolAddress((void**)&WvT, g_WvT);
    cudaGetSymbolAddress((void**)&Qp,  g_Qp);
    cudaGetSymbolAddress((void**)&Kp,  g_Kp);
    cudaGetSymbolAddress((void**)&Vp,  g_Vp);
    cudaGetSymbolAddress((void**)&Sch, g_Sch);
    cudaGetSymbolAddress((void**)&Ph,  g_Ph);

    cudaFuncSetAttribute(hgemm<true,  false, true,  true >, cudaFuncAttributeMaxDynamicSharedMemorySize, GEMM_SMEM);
    cudaFuncSetAttribute(hgemm<false, true,  false, false>, cudaFuncAttributeMaxDynamicSharedMemorySize, GEMM_SMEM);
    cudaFuncSetAttribute(hgemm_mix, cudaFuncAttributeMaxDynamicSharedMemorySize, GEMM_SMEM);

    const long nQKV = (long)BB * SS * DD;

    // 1: combined prep — conversions (z 0-2) + weight transposes (z 3-5)
    {
        dim3 g(1024, 1, 6);
        prep_kernel<<<g, 256>>>(q, k, v, qh, kh, vh,
                                Wq, Wk, Wv, WqT, WkT, WvT, nQKV / 4);
    }

    const dim3 blk(128);

    // 2: Q and K projections (z in {0,1} selects triple)
    {
        dim3 g(DD / 128, (BB * SS) / 128, 2);
        hgemm<true, false, true, true><<<g, blk, GEMM_SMEM>>>(
            qh, WqT, bq, Qp, DD, DD, DD, 1.0f, 0, 0, 0,
            kh, WkT, bk, Kp,
            nullptr, nullptr, nullptr, nullptr);
    }

    // 3: MIXED: scores (1024 CTAs, fp16 out) + V-projection (512 CTAs)
    {
        hgemm_mix<<<1536, blk, GEMM_SMEM>>>(Qp, Kp, Sch, vh, WvT, bv, Vp);
    }

    // 4: Softmax (fp16 -> fp16 probs)
    softmax2048_h<<<BB * SS, 256>>>(Sch, Ph);

    // 5: PV (NN, f32 out): A=Ph [S,S], B=Vp [S,D] k-major; M=2048, N=1024, K=2048
    {
        dim3 g(DD / 128, SS / 128, BB);
        hgemm<false, true, false, false><<<g, blk, GEMM_SMEM>>>(
            Ph, Vp, nullptr, out, DD, SS, DD, 1.0f,
            (long)SS * SS, (long)SS * DD, (long)SS * DD,
            nullptr, nullptr, nullptr, nullptr,
            nullptr, nullptr, nullptr, nullptr);
    }
}